// round 8
// baseline (speedup 1.0000x reference)
#include <cuda_runtime.h>
#include <cstdint>
#include <math.h>

#define NIPV    256
#define NINNER  16
#define NINPUT  784
#define NDIM    64
#define TWO_PI  6.28318530717958647692f
#define NEG_INF __int_as_float(0xff800000)

// ---------------------------------------------------------------------------
__device__ __forceinline__ uint32_t cvt_tf32(float x) {
    uint32_t u; asm("cvt.rna.tf32.f32 %0, %1;" : "=r"(u) : "f"(x)); return u;
}
__device__ __forceinline__ void mma8(float* c, const uint32_t* a, uint32_t b0, uint32_t b1) {
    asm volatile("mma.sync.aligned.m16n8k8.row.col.f32.tf32.tf32.f32 "
        "{%0,%1,%2,%3}, {%4,%5,%6,%7}, {%8,%9}, {%0,%1,%2,%3};"
        : "+f"(c[0]), "+f"(c[1]), "+f"(c[2]), "+f"(c[3])
        : "r"(a[0]), "r"(a[1]), "r"(a[2]), "r"(a[3]), "r"(b0), "r"(b1));
}
__device__ __forceinline__ float fast_tanh(float x) {
    float e = __expf(2.0f * x);
    return 1.0f - __fdividef(2.0f, e + 1.0f);
}
__device__ __forceinline__ float softplus_f(float x) {
    return fmaxf(x, 0.f) + log1pf(__expf(-fabsf(x)));
}
// 64x64 fp32 tile: LDG into 16 regs
__device__ __forceinline__ void load_tile4(float4 v[4], const float* src, int t) {
    const float4* s4 = (const float4*)src;
#pragma unroll
    for (int r = 0; r < 4; r++) v[r] = s4[t + 256 * r];
}
// store tile in A-fragment order: [ks][m][lane][vi]  (4096 u32)
__device__ __forceinline__ void store_tileA(uint32_t* dst, const float4 v[4], int t) {
#pragma unroll
    for (int r = 0; r < 4; r++) {
        int f4 = t + 256 * r;
        int row = f4 >> 4, c4 = f4 & 15;
        int ks = c4 >> 1, m = row >> 4, rr = row & 15;
        int vi = ((rr >= 8) ? 1 : 0) + ((c4 & 1) ? 2 : 0);
        uint32_t* base = dst + (((ks * 4 + m) * 32 + (rr & 7) * 4) << 2) + vi;
        base[0]  = cvt_tf32(v[r].x);
        base[4]  = cvt_tf32(v[r].y);
        base[8]  = cvt_tf32(v[r].z);
        base[12] = cvt_tf32(v[r].w);
    }
}
// A fragments for 4 m-tiles at k-step ks: 4x LDS.128, conflict-free
__device__ __forceinline__ void load_aF(uint32_t a[4][4], const uint32_t* TB,
                                        int ks, int lane) {
#pragma unroll
    for (int m = 0; m < 4; m++) {
        uint4 v = *(const uint4*)(TB + (((ks * 4 + m) * 32 + lane) << 2));
        a[m][0] = v.x; a[m][1] = v.y; a[m][2] = v.z; a[m][3] = v.w;
    }
}
// B element (k, n) -> fragment-order slot: [ks][nblk][lane][vi]
__device__ __forceinline__ void store_b(uint32_t* Bf, int k, int n, float val) {
    int ks = k >> 3, kk = k & 7;
    Bf[(((ks * 32 + (n >> 3)) * 32 + (n & 7) * 4 + (kk & 3)) << 1) + (kk >= 4 ? 1 : 0)]
        = cvt_tf32(val);
}

// ===========================================================================
// Inner path. smem(u32/f): TB0 4096u | TB1 4096u | Bf 16384u | w2s 512f
//   | lws 256f | vbuf 2080f | lseb 8f  -> 27,432 floats = 109,728 B
// ===========================================================================
__device__ void inner_path(float* sm, int bx,
    const float* __restrict__ z, const float* __restrict__ log_w,
    const float* __restrict__ icoef, const float* __restrict__ w1,
    const float* __restrict__ w2, float* __restrict__ out)
{
    uint32_t* TB0 = (uint32_t*)sm;
    uint32_t* TB1 = TB0 + 4096;
    uint32_t* Bf  = TB0 + 8192;
    float* w2s  = sm + 24576;
    float* lws  = sm + 25088;
    float* vbuf = sm + 25344;   // [8][260]
    float* lseb = sm + 27424;

    const int t = threadIdx.x, lane = t & 31, w = t >> 5;
    const int gid = lane >> 2, tig = lane & 3;
    const int i = bx >> 1, gh = bx & 1;

    float4 tr[4];
    load_tile4(tr, w1 + (size_t)(gh * 8) * 4096, t);

    const float zi = z[i], zn = z[t];
#pragma unroll
    for (int k = 0; k < 32; k++) {
        float s, c;
        __sincosf(TWO_PI * fmaf(zi, icoef[k], zn * icoef[32 + k]), &s, &c);
        store_b(Bf, k, t, c);
        store_b(Bf, k + 32, t, s);
    }
    for (int idx = t; idx < 512; idx += 256) w2s[idx] = w2[gh * 512 + idx];
    lws[t] = log_w[t];
    store_tileA(TB0, tr, t);
    __syncthreads();

#pragma unroll 1
    for (int gl = 0; gl < 8; gl++) {
        const uint32_t* TB = (gl & 1) ? TB1 : TB0;
        if (gl < 7) load_tile4(tr, w1 + (size_t)(gh * 8 + gl + 1) * 4096, t);

        float cfr[4][4][4];
#pragma unroll
        for (int m = 0; m < 4; m++)
#pragma unroll
            for (int nf = 0; nf < 4; nf++)
#pragma unroll
                for (int jj = 0; jj < 4; jj++) cfr[m][nf][jj] = 0.f;

#pragma unroll
        for (int ks = 0; ks < 8; ks++) {
            uint32_t a[4][4];
            load_aF(a, TB, ks, lane);
#pragma unroll
            for (int nf = 0; nf < 4; nf++) {
                uint2 bv = *(const uint2*)(Bf + (((ks * 32 + (4 * w + nf)) * 32 + lane) << 1));
#pragma unroll
                for (int m = 0; m < 4; m++) mma8(cfr[m][nf], a[m], bv.x, bv.y);
            }
        }
        if (gl < 7) store_tileA((gl & 1) ? TB0 : TB1, tr, t);

        // epilogue: acc_n = sum_d w2[g,d] * tanh(s[d,n])
        float pc[4][2] = {{0.f,0.f},{0.f,0.f},{0.f,0.f},{0.f,0.f}};
#pragma unroll
        for (int m = 0; m < 4; m++) {
            float w2a = w2s[gl * 64 + 16 * m + gid];
            float w2b = w2s[gl * 64 + 16 * m + gid + 8];
#pragma unroll
            for (int nf = 0; nf < 4; nf++) {
                pc[nf][0] += w2a * fast_tanh(cfr[m][nf][0]) + w2b * fast_tanh(cfr[m][nf][2]);
                pc[nf][1] += w2a * fast_tanh(cfr[m][nf][1]) + w2b * fast_tanh(cfr[m][nf][3]);
            }
        }
#pragma unroll
        for (int nf = 0; nf < 4; nf++)
#pragma unroll
            for (int j2 = 0; j2 < 2; j2++) {
#pragma unroll
                for (int o = 4; o <= 16; o <<= 1)
                    pc[nf][j2] += __shfl_xor_sync(0xffffffffu, pc[nf][j2], o);
            }
        if (gid == 0) {
#pragma unroll
            for (int nf = 0; nf < 4; nf++)
#pragma unroll
                for (int j2 = 0; j2 < 2; j2++) {
                    int n = 32 * w + nf * 8 + 2 * tig + j2;
                    vbuf[gl * 260 + n] = lws[n] - softplus_f(pc[nf][j2]);
                }
        }
        __syncthreads();   // next-buffer STS visible; last iter: vbuf final
    }

    // lse over n (=j) per g: warp w handles row w
    {
        const float* row = vbuf + w * 260;
        float mx = NEG_INF;
#pragma unroll
        for (int k = 0; k < 8; k++) mx = fmaxf(mx, row[lane + 32 * k]);
#pragma unroll
        for (int o = 16; o > 0; o >>= 1) mx = fmaxf(mx, __shfl_xor_sync(0xffffffffu, mx, o));
        float ssum = 0.f;
#pragma unroll
        for (int k = 0; k < 8; k++) ssum += __expf(row[lane + 32 * k] - mx);
#pragma unroll
        for (int o = 16; o > 0; o >>= 1) ssum += __shfl_xor_sync(0xffffffffu, ssum, o);
        if (lane == 0) lseb[w] = mx + __logf(ssum);
    }
    __syncthreads();

#pragma unroll
    for (int lg = 0; lg < 8; lg++)
        out[(size_t)(gh * 8 + lg) * (NIPV * NIPV) + (size_t)t * NIPV + i] =
            __expf(vbuf[lg * 260 + t] - lseb[lg]);
}

// ===========================================================================
// Input path. smem: TB 4096u | his 16384u | tbuf 5120f | lseb 256f
//   -> 25,856 floats = 103,424 B
// ===========================================================================
__device__ void input_path(float* sm, int g,
    const float* __restrict__ z, const float* __restrict__ icoef,
    const float* __restrict__ w1, const float* __restrict__ w2,
    float* __restrict__ out)
{
    uint32_t* TB  = (uint32_t*)sm;
    uint32_t* his = (uint32_t*)sm + 4096;     // B-frag layout
    float* tbuf = sm + 20480;                 // [256][20]
    float* lseb = sm + 25600;

    const int t = threadIdx.x, lane = t & 31, w = t >> 5;
    const int gid = lane >> 2, tig = lane & 3;
    const float* w2g = w2 + (size_t)g * 16384;

    float4 tr[4];
    load_tile4(tr, w1 + (size_t)g * 4096, t);
    store_tileA(TB, tr, t);
    __syncthreads();

    float znv[4];
#pragma unroll
    for (int nf = 0; nf < 4; nf++) znv[nf] = __ldg(z + 32 * w + nf * 8 + gid);

    // ---- stage 1: hi = tanh(w1g @ ff); B computed on the fly (sincos)
    {
        float cfr[4][4][4];
#pragma unroll
        for (int m = 0; m < 4; m++)
#pragma unroll
            for (int nf = 0; nf < 4; nf++)
#pragma unroll
                for (int jj = 0; jj < 4; jj++) cfr[m][nf][jj] = 0.f;

#pragma unroll
        for (int ks = 0; ks < 8; ks++) {
            uint32_t a[4][4];
            load_aF(a, TB, ks, lane);
            const int k0 = ks * 8 + tig;
            const float cf0 = __ldg(icoef + (k0 & 31));
            const float cf1 = __ldg(icoef + ((k0 + 4) & 31));
#pragma unroll
            for (int nf = 0; nf < 4; nf++) {
                float s0, c0, s1, c1;
                __sincosf(TWO_PI * znv[nf] * cf0, &s0, &c0);
                __sincosf(TWO_PI * znv[nf] * cf1, &s1, &c1);
                uint32_t b0 = cvt_tf32((ks < 4) ? c0 : s0);
                uint32_t b1 = cvt_tf32((ks < 4) ? c1 : s1);
#pragma unroll
                for (int m = 0; m < 4; m++) mma8(cfr[m][nf], a[m], b0, b1);
            }
        }
        load_tile4(tr, w2g, t);   // prefetch chunk 0
#pragma unroll
        for (int m = 0; m < 4; m++)
#pragma unroll
            for (int nf = 0; nf < 4; nf++)
#pragma unroll
                for (int jj = 0; jj < 4; jj++) {
                    int d = 16 * m + gid + 8 * (jj >> 1);
                    int n = 32 * w + nf * 8 + 2 * tig + (jj & 1);
                    store_b(his, d, n, fast_tanh(cfr[m][nf][jj]));
                }
    }
    __syncthreads();
    store_tileA(TB, tr, t);
    __syncthreads();

    float mcol[8], scol[8];
#pragma unroll
    for (int q = 0; q < 8; q++) { mcol[q] = NEG_INF; scol[q] = 0.f; }

    float* og = out + (size_t)g * (NIPV * 256);
    float4* og4 = (float4*)og;

#pragma unroll 1
    for (int cb = 0; cb < 4; cb++) {
        float c2[4][4][4];
#pragma unroll
        for (int m = 0; m < 4; m++)
#pragma unroll
            for (int nf = 0; nf < 4; nf++)
#pragma unroll
                for (int jj = 0; jj < 4; jj++) c2[m][nf][jj] = 0.f;

#pragma unroll
        for (int ks = 0; ks < 8; ks++) {
            uint32_t a[4][4];
            load_aF(a, TB, ks, lane);
#pragma unroll
            for (int nf = 0; nf < 4; nf++) {
                uint2 bv = *(const uint2*)(his + (((ks * 32 + (4 * w + nf)) * 32 + lane) << 1));
#pragma unroll
                for (int m = 0; m < 4; m++) mma8(c2[m][nf], a[m], bv.x, bv.y);
            }
        }
        if (cb < 3) load_tile4(tr, w2g + (size_t)(cb + 1) * 4096, t);

        // online lse per column
#pragma unroll
        for (int nf = 0; nf < 4; nf++)
#pragma unroll
            for (int j2 = 0; j2 < 2; j2++) {
                float lm = NEG_INF;
#pragma unroll
                for (int m = 0; m < 4; m++) {
                    lm = fmaxf(lm, c2[m][nf][j2]);
                    lm = fmaxf(lm, c2[m][nf][2 + j2]);
                }
                float ls = 0.f;
#pragma unroll
                for (int m = 0; m < 4; m++) {
                    ls += __expf(c2[m][nf][j2] - lm);
                    ls += __expf(c2[m][nf][2 + j2] - lm);
                }
                int q = nf * 2 + j2;
                float nm = fmaxf(mcol[q], lm);
                scol[q] = scol[q] * __expf(mcol[q] - nm) + ls * __expf(lm - nm);
                mcol[q] = nm;
            }

        // write rounds: one 16-col m-tile at a time through tbuf
#pragma unroll
        for (int m = 0; m < 4; m++) {
#pragma unroll
            for (int nf = 0; nf < 4; nf++)
#pragma unroll
                for (int jj = 0; jj < 4; jj++) {
                    int cl = gid + 8 * (jj >> 1);
                    int n = 32 * w + nf * 8 + 2 * tig + (jj & 1);
                    tbuf[n * 20 + cl] = c2[m][nf][jj];
                }
            __syncthreads();
#pragma unroll
            for (int r = 0; r < 4; r++) {
                int idx = t + 256 * r;
                int n = idx >> 2, c4 = idx & 3;
                float4 v = *(float4*)(tbuf + n * 20 + c4 * 4);
                og4[(size_t)n * 64 + cb * 16 + m * 4 + c4] = v;
            }
            __syncthreads();
        }
        if (cb < 3) { store_tileA(TB, tr, t); __syncthreads(); }
    }

    // merge (max,sum) across gid lanes
#pragma unroll
    for (int q = 0; q < 8; q++) {
#pragma unroll
        for (int o = 4; o <= 16; o <<= 1) {
            float mo = __shfl_xor_sync(0xffffffffu, mcol[q], o);
            float so = __shfl_xor_sync(0xffffffffu, scol[q], o);
            float nm = fmaxf(mcol[q], mo);
            scol[q] = scol[q] * __expf(mcol[q] - nm) + so * __expf(mo - nm);
            mcol[q] = nm;
        }
    }
    if (gid == 0) {
#pragma unroll
        for (int nf = 0; nf < 4; nf++)
#pragma unroll
            for (int j2 = 0; j2 < 2; j2++)
                lseb[32 * w + nf * 8 + 2 * tig + j2] =
                    mcol[nf * 2 + j2] + __logf(scol[nf * 2 + j2]);
    }
    __syncthreads();

    // fused log-softmax subtract (L2-hot reread)
#pragma unroll 4
    for (int r = 0; r < 64; r++) {
        int idx = t + 256 * r;
        float l = lseb[idx >> 6];
        float4 v = og4[idx];
        v.x -= l; v.y -= l; v.z -= l; v.w -= l;
        og4[idx] = v;
    }
}

// ===========================================================================
__global__ __launch_bounds__(256, 2) void mega2_kernel(
    const float* __restrict__ z, const float* __restrict__ log_w,
    const float* __restrict__ icoef, const float* __restrict__ iw1,
    const float* __restrict__ iw2,
    const float* __restrict__ incoef, const float* __restrict__ inw1,
    const float* __restrict__ inw2,
    float* __restrict__ out_inner, float* __restrict__ out_input)
{
    extern __shared__ float sm[];
    if (blockIdx.x < 512)
        inner_path(sm, blockIdx.x, z, log_w, icoef, iw1, iw2, out_inner);
    else
        input_path(sm, blockIdx.x - 512, z, incoef, inw1, inw2, out_input);
}

extern "C" void kernel_launch(void* const* d_in, const int* in_sizes, int n_in,
                              void* d_out, int out_size) {
    const float* z      = (const float*)d_in[0];
    const float* log_w  = (const float*)d_in[1];
    const float* icoef  = (const float*)d_in[2];
    const float* iw1    = (const float*)d_in[3];
    const float* iw2    = (const float*)d_in[4];
    const float* incoef = (const float*)d_in[5];
    const float* inw1   = (const float*)d_in[6];
    const float* inw2   = (const float*)d_in[7];

    float* out = (float*)d_out;
    float* out_input = out + (size_t)NINNER * NIPV * NIPV;

    const int SMEM = 27432 * (int)sizeof(float);   // 109,728 B
    cudaFuncSetAttribute(mega2_kernel, cudaFuncAttributeMaxDynamicSharedMemorySize, SMEM);

    mega2_kernel<<<512 + NINPUT, 256, SMEM>>>(z, log_w, icoef, iw1, iw2,
                                              incoef, inw1, inw2, out, out_input);
}

// round 9
// speedup vs baseline: 1.1433x; 1.1433x over previous
#include <cuda_runtime.h>
#include <cstdint>
#include <math.h>

#define NIPV    256
#define NINNER  16
#define NINPUT  784
#define NDIM    64
#define TWO_PI  6.28318530717958647692f
#define NEG_INF __int_as_float(0xff800000)

// ---------------------------------------------------------------------------
__device__ __forceinline__ uint32_t cvt_tf32(float x) {
    uint32_t u; asm("cvt.rna.tf32.f32 %0, %1;" : "=r"(u) : "f"(x)); return u;
}
__device__ __forceinline__ void mma8(float* c, const uint32_t* a, uint32_t b0, uint32_t b1) {
    asm volatile("mma.sync.aligned.m16n8k8.row.col.f32.tf32.tf32.f32 "
        "{%0,%1,%2,%3}, {%4,%5,%6,%7}, {%8,%9}, {%0,%1,%2,%3};"
        : "+f"(c[0]), "+f"(c[1]), "+f"(c[2]), "+f"(c[3])
        : "r"(a[0]), "r"(a[1]), "r"(a[2]), "r"(a[3]), "r"(b0), "r"(b1));
}
__device__ __forceinline__ float fast_tanh(float x) {
    float e = __expf(2.0f * x);
    return 1.0f - __fdividef(2.0f, e + 1.0f);
}
__device__ __forceinline__ float softplus_f(float x) {
    return fmaxf(x, 0.f) + log1pf(__expf(-fabsf(x)));
}
// 64x64 fp32 tile: LDG into 16 regs
__device__ __forceinline__ void load_tile4(float4 v[4], const float* src, int t) {
    const float4* s4 = (const float4*)src;
#pragma unroll
    for (int r = 0; r < 4; r++) v[r] = s4[t + 256 * r];
}
// R7 layout: row-major, stride 68 (conflict-free scalar access)
__device__ __forceinline__ void store_tile68(uint32_t* dst, const float4 v[4], int t) {
#pragma unroll
    for (int r = 0; r < 4; r++) {
        int f4 = t + 256 * r;
        int row = f4 >> 4, c4 = f4 & 15;
        uint32_t* d = dst + row * 68 + c4 * 4;
        d[0] = cvt_tf32(v[r].x); d[1] = cvt_tf32(v[r].y);
        d[2] = cvt_tf32(v[r].z); d[3] = cvt_tf32(v[r].w);
    }
}
// A fragments (row-major operand) from stride-68 tile: 4 scattered LDS.32 x4
__device__ __forceinline__ void load_a68(uint32_t a[4][4], const uint32_t* W,
                                         int ks, int gid, int tig) {
#pragma unroll
    for (int m = 0; m < 4; m++) {
        int r0 = (16 * m + gid) * 68 + ks * 8 + tig;
        a[m][0] = W[r0];            a[m][1] = W[r0 + 8 * 68];
        a[m][2] = W[r0 + 4];        a[m][3] = W[r0 + 8 * 68 + 4];
    }
}
// B element (k, n) -> R7-style layout [k][n] stride 264 (conflict-free)
__device__ __forceinline__ void store_b264(uint32_t* Bf, int k, int n, float val) {
    Bf[k * 264 + n] = cvt_tf32(val);
}
// --- inner-path B (w1^T) frag layout: word = (ks*8+nb)*66 + lane*2 + hi ----
// stage w1 tile [64 d][64 k] -> B-frag layout (B[k][n=d])
__device__ __forceinline__ void store_tileBT(uint32_t* dst, const float4 v[4], int t) {
#pragma unroll
    for (int r = 0; r < 4; r++) {
        int f4 = t + 256 * r;
        int d = f4 >> 4, k4 = f4 & 15;
        int ks = k4 >> 1, hi = k4 & 1, nb = d >> 3, g8 = d & 7;
        uint32_t* base = dst + (ks * 8 + nb) * 66 + g8 * 8 + hi;
        base[0] = cvt_tf32(v[r].x);
        base[2] = cvt_tf32(v[r].y);
        base[4] = cvt_tf32(v[r].z);
        base[6] = cvt_tf32(v[r].w);
    }
}

// ===========================================================================
// Inner path: ff in registers as A (M=256 j), w1^T as B per g (d quarters).
// smem(words): TB0 4224 | TB1 4224 | w2s 512 | lws 256 | vbuf 2080 | lseb 8
//   -> 11,304 words = 45,216 B
// ===========================================================================
__device__ void inner_path(float* sm, int bx,
    const float* __restrict__ z, const float* __restrict__ log_w,
    const float* __restrict__ icoef, const float* __restrict__ w1,
    const float* __restrict__ w2, float* __restrict__ out)
{
    uint32_t* TB0 = (uint32_t*)sm;
    uint32_t* TB1 = TB0 + 4224;
    float* w2s  = sm + 8448;
    float* lws  = sm + 8960;
    float* vbuf = sm + 9216;    // [8][260]
    float* lseb = sm + 11296;

    const int t = threadIdx.x, lane = t & 31, w = t >> 5;
    const int gid = lane >> 2, tig = lane & 3;
    const int i = bx >> 1, gh = bx & 1;

    float4 tr[4];
    load_tile4(tr, w1 + (size_t)(gh * 8) * 4096, t);

    const float zi = z[i];
    float zjv[4];
#pragma unroll
    for (int k = 0; k < 4; k++) zjv[k] = __ldg(z + 32 * w + gid + 8 * k);

    // A fragments (ff^T): af[mm][ks][vi], vi = ar + 2*ac
    uint32_t af[2][8][4];
#pragma unroll
    for (int km = 0; km < 4; km++)
#pragma unroll
        for (int ac = 0; ac < 2; ac++) {
            int kb = 8 * km + tig + 4 * ac;
            float c0 = __ldg(icoef + kb), c1 = __ldg(icoef + 32 + kb);
#pragma unroll
            for (int mm = 0; mm < 2; mm++)
#pragma unroll
                for (int ar = 0; ar < 2; ar++) {
                    float s, c;
                    __sincosf(TWO_PI * fmaf(zi, c0, zjv[mm * 2 + ar] * c1), &s, &c);
                    af[mm][km][ar + 2 * ac]     = cvt_tf32(c);
                    af[mm][km + 4][ar + 2 * ac] = cvt_tf32(s);
                }
        }

    for (int idx = t; idx < 512; idx += 256) w2s[idx] = w2[gh * 512 + idx];
    lws[t] = log_w[t];
    store_tileBT(TB0, tr, t);
    __syncthreads();

#pragma unroll 1
    for (int gl = 0; gl < 8; gl++) {
        const uint32_t* TB = (gl & 1) ? TB1 : TB0;
        if (gl < 7) load_tile4(tr, w1 + (size_t)(gh * 8 + gl + 1) * 4096, t);

        float pc[2][2] = {{0.f, 0.f}, {0.f, 0.f}};
#pragma unroll
        for (int q = 0; q < 4; q++) {
            float C[2][2][4];
#pragma unroll
            for (int mm = 0; mm < 2; mm++)
#pragma unroll
                for (int nb = 0; nb < 2; nb++)
#pragma unroll
                    for (int jj = 0; jj < 4; jj++) C[mm][nb][jj] = 0.f;
#pragma unroll
            for (int ks = 0; ks < 8; ks++) {
                uint2 b0 = *(const uint2*)(TB + (ks * 8 + 2 * q)     * 66 + lane * 2);
                uint2 b1 = *(const uint2*)(TB + (ks * 8 + 2 * q + 1) * 66 + lane * 2);
                mma8(C[0][0], af[0][ks], b0.x, b0.y);
                mma8(C[0][1], af[0][ks], b1.x, b1.y);
                mma8(C[1][0], af[1][ks], b0.x, b0.y);
                mma8(C[1][1], af[1][ks], b1.x, b1.y);
            }
            // accumulate d-partials: d = 16q + 8nb + 2tig + (jj&1)
#pragma unroll
            for (int mm = 0; mm < 2; mm++)
#pragma unroll
                for (int nb = 0; nb < 2; nb++)
#pragma unroll
                    for (int jj = 0; jj < 4; jj++) {
                        int d = 16 * q + 8 * nb + 2 * tig + (jj & 1);
                        pc[mm][jj >> 1] += w2s[gl * 64 + d] * fast_tanh(C[mm][nb][jj]);
                    }
        }
        // reduce over tig lanes (xor 1,2); j = 32w + 16mm + 8ar + gid
#pragma unroll
        for (int mm = 0; mm < 2; mm++)
#pragma unroll
            for (int ar = 0; ar < 2; ar++) {
                pc[mm][ar] += __shfl_xor_sync(0xffffffffu, pc[mm][ar], 1);
                pc[mm][ar] += __shfl_xor_sync(0xffffffffu, pc[mm][ar], 2);
            }
        if (tig == 0) {
#pragma unroll
            for (int mm = 0; mm < 2; mm++)
#pragma unroll
                for (int ar = 0; ar < 2; ar++) {
                    int j = 32 * w + 16 * mm + 8 * ar + gid;
                    vbuf[gl * 260 + j] = lws[j] - softplus_f(pc[mm][ar]);
                }
        }
        if (gl < 7) store_tileBT((gl & 1) ? TB0 : TB1, tr, t);
        __syncthreads();
    }

    // lse over j per g: warp w handles row w
    {
        const float* row = vbuf + w * 260;
        float mx = NEG_INF;
#pragma unroll
        for (int k = 0; k < 8; k++) mx = fmaxf(mx, row[lane + 32 * k]);
#pragma unroll
        for (int o = 16; o > 0; o >>= 1) mx = fmaxf(mx, __shfl_xor_sync(0xffffffffu, mx, o));
        float ssum = 0.f;
#pragma unroll
        for (int k = 0; k < 8; k++) ssum += __expf(row[lane + 32 * k] - mx);
#pragma unroll
        for (int o = 16; o > 0; o >>= 1) ssum += __shfl_xor_sync(0xffffffffu, ssum, o);
        if (lane == 0) lseb[w] = mx + __logf(ssum);
    }
    __syncthreads();

#pragma unroll
    for (int lg = 0; lg < 8; lg++)
        out[(size_t)(gh * 8 + lg) * (NIPV * NIPV) + (size_t)t * NIPV + i] =
            __expf(vbuf[lg * 260 + t] - lseb[lg]);
}

// ===========================================================================
// Input path (R7 verbatim). smem(words): TB 4352 | his 64*264 | tbuf 5120
//   | lseb 256  -> 26,624 words = 106,496 B
// ===========================================================================
__device__ void input_path(float* sm, int g,
    const float* __restrict__ z, const float* __restrict__ icoef,
    const float* __restrict__ w1, const float* __restrict__ w2,
    float* __restrict__ out)
{
    uint32_t* TB  = (uint32_t*)sm;
    uint32_t* his = (uint32_t*)sm + 4352;     // [64][264]
    float* tbuf = sm + 21248;                 // [256][20]
    float* lseb = sm + 26368;

    const int t = threadIdx.x, lane = t & 31, w = t >> 5;
    const int gid = lane >> 2, tig = lane & 3;
    const float* w2g = w2 + (size_t)g * 16384;

    float4 tr[4];
    load_tile4(tr, w1 + (size_t)g * 4096, t);
    store_tile68(TB, tr, t);
    __syncthreads();

    float znv[4];
#pragma unroll
    for (int nf = 0; nf < 4; nf++) znv[nf] = __ldg(z + 32 * w + nf * 8 + gid);

    // ---- stage 1: hi = tanh(w1g @ ff); B computed on the fly (sincos)
    {
        float cfr[4][4][4];
#pragma unroll
        for (int m = 0; m < 4; m++)
#pragma unroll
            for (int nf = 0; nf < 4; nf++)
#pragma unroll
                for (int jj = 0; jj < 4; jj++) cfr[m][nf][jj] = 0.f;

#pragma unroll
        for (int ks = 0; ks < 8; ks++) {
            uint32_t a[4][4];
            load_a68(a, TB, ks, gid, tig);
            const int k0 = ks * 8 + tig;
            const float cf0 = __ldg(icoef + (k0 & 31));
            const float cf1 = __ldg(icoef + ((k0 + 4) & 31));
#pragma unroll
            for (int nf = 0; nf < 4; nf++) {
                float s0, c0, s1, c1;
                __sincosf(TWO_PI * znv[nf] * cf0, &s0, &c0);
                __sincosf(TWO_PI * znv[nf] * cf1, &s1, &c1);
                uint32_t b0 = cvt_tf32((ks < 4) ? c0 : s0);
                uint32_t b1 = cvt_tf32((ks < 4) ? c1 : s1);
#pragma unroll
                for (int m = 0; m < 4; m++) mma8(cfr[m][nf], a[m], b0, b1);
            }
        }
        load_tile4(tr, w2g, t);   // prefetch chunk 0
#pragma unroll
        for (int m = 0; m < 4; m++)
#pragma unroll
            for (int nf = 0; nf < 4; nf++)
#pragma unroll
                for (int jj = 0; jj < 4; jj++) {
                    int d = 16 * m + gid + 8 * (jj >> 1);
                    int n = 32 * w + nf * 8 + 2 * tig + (jj & 1);
                    store_b264(his, d, n, fast_tanh(cfr[m][nf][jj]));
                }
    }
    __syncthreads();
    store_tile68(TB, tr, t);
    __syncthreads();

    float mcol[8], scol[8];
#pragma unroll
    for (int q = 0; q < 8; q++) { mcol[q] = NEG_INF; scol[q] = 0.f; }

    float* og = out + (size_t)g * (NIPV * 256);
    float4* og4 = (float4*)og;

#pragma unroll 1
    for (int cb = 0; cb < 4; cb++) {
        float c2[4][4][4];
#pragma unroll
        for (int m = 0; m < 4; m++)
#pragma unroll
            for (int nf = 0; nf < 4; nf++)
#pragma unroll
                for (int jj = 0; jj < 4; jj++) c2[m][nf][jj] = 0.f;

#pragma unroll
        for (int ks = 0; ks < 8; ks++) {
            uint32_t a[4][4];
            load_a68(a, TB, ks, gid, tig);
#pragma unroll
            for (int nf = 0; nf < 4; nf++) {
                uint32_t b0 = his[(ks * 8 + tig)     * 264 + 32 * w + nf * 8 + gid];
                uint32_t b1 = his[(ks * 8 + tig + 4) * 264 + 32 * w + nf * 8 + gid];
#pragma unroll
                for (int m = 0; m < 4; m++) mma8(c2[m][nf], a[m], b0, b1);
            }
        }
        if (cb < 3) load_tile4(tr, w2g + (size_t)(cb + 1) * 4096, t);

        // online lse per column
#pragma unroll
        for (int nf = 0; nf < 4; nf++)
#pragma unroll
            for (int j2 = 0; j2 < 2; j2++) {
                float lm = NEG_INF;
#pragma unroll
                for (int m = 0; m < 4; m++) {
                    lm = fmaxf(lm, c2[m][nf][j2]);
                    lm = fmaxf(lm, c2[m][nf][2 + j2]);
                }
                float ls = 0.f;
#pragma unroll
                for (int m = 0; m < 4; m++) {
                    ls += __expf(c2[m][nf][j2] - lm);
                    ls += __expf(c2[m][nf][2 + j2] - lm);
                }
                int q = nf * 2 + j2;
                float nm = fmaxf(mcol[q], lm);
                scol[q] = scol[q] * __expf(mcol[q] - nm) + ls * __expf(lm - nm);
                mcol[q] = nm;
            }

        // write rounds: one 16-col m-tile at a time through tbuf
#pragma unroll
        for (int m = 0; m < 4; m++) {
#pragma unroll
            for (int nf = 0; nf < 4; nf++)
#pragma unroll
                for (int jj = 0; jj < 4; jj++) {
                    int cl = gid + 8 * (jj >> 1);
                    int n = 32 * w + nf * 8 + 2 * tig + (jj & 1);
                    tbuf[n * 20 + cl] = c2[m][nf][jj];
                }
            __syncthreads();
#pragma unroll
            for (int r = 0; r < 4; r++) {
                int idx = t + 256 * r;
                int n = idx >> 2, c4 = idx & 3;
                float4 v = *(float4*)(tbuf + n * 20 + c4 * 4);
                og4[(size_t)n * 64 + cb * 16 + m * 4 + c4] = v;
            }
            __syncthreads();
        }
        if (cb < 3) { store_tile68(TB, tr, t); __syncthreads(); }
    }

    // merge (max,sum) across gid lanes
#pragma unroll
    for (int q = 0; q < 8; q++) {
#pragma unroll
        for (int o = 4; o <= 16; o <<= 1) {
            float mo = __shfl_xor_sync(0xffffffffu, mcol[q], o);
            float so = __shfl_xor_sync(0xffffffffu, scol[q], o);
            float nm = fmaxf(mcol[q], mo);
            scol[q] = scol[q] * __expf(mcol[q] - nm) + so * __expf(mo - nm);
            mcol[q] = nm;
        }
    }
    if (gid == 0) {
#pragma unroll
        for (int nf = 0; nf < 4; nf++)
#pragma unroll
            for (int j2 = 0; j2 < 2; j2++)
                lseb[32 * w + nf * 8 + 2 * tig + j2] =
                    mcol[nf * 2 + j2] + __logf(scol[nf * 2 + j2]);
    }
    __syncthreads();

    // fused log-softmax subtract (L2-hot reread)
#pragma unroll 4
    for (int r = 0; r < 64; r++) {
        int idx = t + 256 * r;
        float l = lseb[idx >> 6];
        float4 v = og4[idx];
        v.x -= l; v.y -= l; v.z -= l; v.w -= l;
        og4[idx] = v;
    }
}

// ===========================================================================
__global__ __launch_bounds__(256, 2) void mega2_kernel(
    const float* __restrict__ z, const float* __restrict__ log_w,
    const float* __restrict__ icoef, const float* __restrict__ iw1,
    const float* __restrict__ iw2,
    const float* __restrict__ incoef, const float* __restrict__ inw1,
    const float* __restrict__ inw2,
    float* __restrict__ out_inner, float* __restrict__ out_input)
{
    extern __shared__ float sm[];
    if (blockIdx.x < 512)
        inner_path(sm, blockIdx.x, z, log_w, icoef, iw1, iw2, out_inner);
    else
        input_path(sm, blockIdx.x - 512, z, incoef, inw1, inw2, out_input);
}

extern "C" void kernel_launch(void* const* d_in, const int* in_sizes, int n_in,
                              void* d_out, int out_size) {
    const float* z      = (const float*)d_in[0];
    const float* log_w  = (const float*)d_in[1];
    const float* icoef  = (const float*)d_in[2];
    const float* iw1    = (const float*)d_in[3];
    const float* iw2    = (const float*)d_in[4];
    const float* incoef = (const float*)d_in[5];
    const float* inw1   = (const float*)d_in[6];
    const float* inw2   = (const float*)d_in[7];

    float* out = (float*)d_out;
    float* out_input = out + (size_t)NINNER * NIPV * NIPV;

    const int SMEM = 26624 * (int)sizeof(float);   // 106,496 B (input path max)
    cudaFuncSetAttribute(mega2_kernel, cudaFuncAttributeMaxDynamicSharedMemorySize, SMEM);

    mega2_kernel<<<512 + NINPUT, 256, SMEM>>>(z, log_w, icoef, iw1, iw2,
                                              incoef, inw1, inw2, out, out_input);
}

// round 10
// speedup vs baseline: 1.1581x; 1.0130x over previous
#include <cuda_runtime.h>
#include <cstdint>
#include <math.h>

#define NIPV    256
#define NINNER  16
#define NINPUT  784
#define NDIM    64
#define TWO_PI  6.28318530717958647692f
#define NEG_INF __int_as_float(0xff800000)

// ---------------------------------------------------------------------------
__device__ __forceinline__ uint32_t cvt_tf32(float x) {
    uint32_t u; asm("cvt.rna.tf32.f32 %0, %1;" : "=r"(u) : "f"(x)); return u;
}
__device__ __forceinline__ void mma8(float* c, const uint32_t* a, uint32_t b0, uint32_t b1) {
    asm volatile("mma.sync.aligned.m16n8k8.row.col.f32.tf32.tf32.f32 "
        "{%0,%1,%2,%3}, {%4,%5,%6,%7}, {%8,%9}, {%0,%1,%2,%3};"
        : "+f"(c[0]), "+f"(c[1]), "+f"(c[2]), "+f"(c[3])
        : "r"(a[0]), "r"(a[1]), "r"(a[2]), "r"(a[3]), "r"(b0), "r"(b1));
}
__device__ __forceinline__ float fast_tanh(float x) {
    float e = __expf(2.0f * x);
    return 1.0f - __fdividef(2.0f, e + 1.0f);
}
__device__ __forceinline__ float softplus_f(float x) {
    return fmaxf(x, 0.f) + log1pf(__expf(-fabsf(x)));
}
// 64x64 fp32 tile: LDG into 16 regs
__device__ __forceinline__ void load_tile4(float4 v[4], const float* src, int t) {
    const float4* s4 = (const float4*)src;
#pragma unroll
    for (int r = 0; r < 4; r++) v[r] = s4[t + 256 * r];
}
// stage [64 rows][64 k] tile as B-operand frags: word (ks*8+nb)*66 + row8*8 + hi
__device__ __forceinline__ void store_tileBT(uint32_t* dst, const float4 v[4], int t) {
#pragma unroll
    for (int r = 0; r < 4; r++) {
        int f4 = t + 256 * r;
        int d = f4 >> 4, k4 = f4 & 15;
        int ks = k4 >> 1, hi = k4 & 1, nb = d >> 3, g8 = d & 7;
        uint32_t* base = dst + (ks * 8 + nb) * 66 + g8 * 8 + hi;
        base[0] = cvt_tf32(v[r].x);
        base[2] = cvt_tf32(v[r].y);
        base[4] = cvt_tf32(v[r].z);
        base[6] = cvt_tf32(v[r].w);
    }
}

// ===========================================================================
// Inner path (R9-verified): ff regs as A, w1^T as B per g, d quarters.
// smem(words): TB0 4224 | TB1 4224 | w2s 512 | lws 256 | vbuf 2080 | lseb 8
// ===========================================================================
__device__ void inner_path(float* sm, int bx,
    const float* __restrict__ z, const float* __restrict__ log_w,
    const float* __restrict__ icoef, const float* __restrict__ w1,
    const float* __restrict__ w2, float* __restrict__ out)
{
    uint32_t* TB0 = (uint32_t*)sm;
    uint32_t* TB1 = TB0 + 4224;
    float* w2s  = sm + 8448;
    float* lws  = sm + 8960;
    float* vbuf = sm + 9216;    // [8][260]
    float* lseb = sm + 11296;

    const int t = threadIdx.x, lane = t & 31, w = t >> 5;
    const int gid = lane >> 2, tig = lane & 3;
    const int i = bx >> 1, gh = bx & 1;

    float4 tr[4];
    load_tile4(tr, w1 + (size_t)(gh * 8) * 4096, t);

    const float zi = z[i];
    float zjv[4];
#pragma unroll
    for (int k = 0; k < 4; k++) zjv[k] = __ldg(z + 32 * w + gid + 8 * k);

    uint32_t af[2][8][4];
#pragma unroll
    for (int km = 0; km < 4; km++)
#pragma unroll
        for (int ac = 0; ac < 2; ac++) {
            int kb = 8 * km + tig + 4 * ac;
            float c0 = __ldg(icoef + kb), c1 = __ldg(icoef + 32 + kb);
#pragma unroll
            for (int mm = 0; mm < 2; mm++)
#pragma unroll
                for (int ar = 0; ar < 2; ar++) {
                    float s, c;
                    __sincosf(TWO_PI * fmaf(zi, c0, zjv[mm * 2 + ar] * c1), &s, &c);
                    af[mm][km][ar + 2 * ac]     = cvt_tf32(c);
                    af[mm][km + 4][ar + 2 * ac] = cvt_tf32(s);
                }
        }

    for (int idx = t; idx < 512; idx += 256) w2s[idx] = w2[gh * 512 + idx];
    lws[t] = log_w[t];
    store_tileBT(TB0, tr, t);
    __syncthreads();

#pragma unroll 1
    for (int gl = 0; gl < 8; gl++) {
        const uint32_t* TB = (gl & 1) ? TB1 : TB0;
        if (gl < 7) load_tile4(tr, w1 + (size_t)(gh * 8 + gl + 1) * 4096, t);

        float pc[2][2] = {{0.f, 0.f}, {0.f, 0.f}};
#pragma unroll
        for (int q = 0; q < 4; q++) {
            float C[2][2][4];
#pragma unroll
            for (int mm = 0; mm < 2; mm++)
#pragma unroll
                for (int nb = 0; nb < 2; nb++)
#pragma unroll
                    for (int jj = 0; jj < 4; jj++) C[mm][nb][jj] = 0.f;
#pragma unroll
            for (int ks = 0; ks < 8; ks++) {
                uint2 b0 = *(const uint2*)(TB + (ks * 8 + 2 * q)     * 66 + lane * 2);
                uint2 b1 = *(const uint2*)(TB + (ks * 8 + 2 * q + 1) * 66 + lane * 2);
                mma8(C[0][0], af[0][ks], b0.x, b0.y);
                mma8(C[0][1], af[0][ks], b1.x, b1.y);
                mma8(C[1][0], af[1][ks], b0.x, b0.y);
                mma8(C[1][1], af[1][ks], b1.x, b1.y);
            }
#pragma unroll
            for (int mm = 0; mm < 2; mm++)
#pragma unroll
                for (int nb = 0; nb < 2; nb++)
#pragma unroll
                    for (int jj = 0; jj < 4; jj++) {
                        int d = 16 * q + 8 * nb + 2 * tig + (jj & 1);
                        pc[mm][jj >> 1] += w2s[gl * 64 + d] * fast_tanh(C[mm][nb][jj]);
                    }
        }
#pragma unroll
        for (int mm = 0; mm < 2; mm++)
#pragma unroll
            for (int ar = 0; ar < 2; ar++) {
                pc[mm][ar] += __shfl_xor_sync(0xffffffffu, pc[mm][ar], 1);
                pc[mm][ar] += __shfl_xor_sync(0xffffffffu, pc[mm][ar], 2);
            }
        if (tig == 0) {
#pragma unroll
            for (int mm = 0; mm < 2; mm++)
#pragma unroll
                for (int ar = 0; ar < 2; ar++) {
                    int j = 32 * w + 16 * mm + 8 * ar + gid;
                    vbuf[gl * 260 + j] = lws[j] - softplus_f(pc[mm][ar]);
                }
        }
        if (gl < 7) store_tileBT((gl & 1) ? TB0 : TB1, tr, t);
        __syncthreads();
    }

    {
        const float* row = vbuf + w * 260;
        float mx = NEG_INF;
#pragma unroll
        for (int k = 0; k < 8; k++) mx = fmaxf(mx, row[lane + 32 * k]);
#pragma unroll
        for (int o = 16; o > 0; o >>= 1) mx = fmaxf(mx, __shfl_xor_sync(0xffffffffu, mx, o));
        float ssum = 0.f;
#pragma unroll
        for (int k = 0; k < 8; k++) ssum += __expf(row[lane + 32 * k] - mx);
#pragma unroll
        for (int o = 16; o > 0; o >>= 1) ssum += __shfl_xor_sync(0xffffffffu, ssum, o);
        if (lane == 0) lseb[w] = mx + __logf(ssum);
    }
    __syncthreads();

#pragma unroll
    for (int lg = 0; lg < 8; lg++)
        out[(size_t)(gh * 8 + lg) * (NIPV * NIPV) + (size_t)t * NIPV + i] =
            __expf(vbuf[lg * 260 + t] - lseb[lg]);
}

// ===========================================================================
// Input path (flipped): A = activations in regs, B = weights via BT layout.
// smem(words): TB 4224 | his 16896 (tbuf [256][20] aliases) | lseb 256
//   -> 21,376 words = 85,504 B
// ===========================================================================
__device__ void input_path(float* sm, int g,
    const float* __restrict__ z, const float* __restrict__ icoef,
    const float* __restrict__ w1, const float* __restrict__ w2,
    float* __restrict__ out)
{
    uint32_t* TB  = (uint32_t*)sm;
    uint32_t* his = (uint32_t*)sm + 4224;    // [64][264]
    float* tbuf = sm + 4224;                 // aliases his: [256][20]
    float* lseb = sm + 21120;

    const int t = threadIdx.x, lane = t & 31, w = t >> 5;
    const int gid = lane >> 2, tig = lane & 3;
    const float* w2g = w2 + (size_t)g * 16384;

    float4 tr[4];
    load_tile4(tr, w1 + (size_t)g * 4096, t);
    store_tileBT(TB, tr, t);
    load_tile4(tr, w2g, t);   // prefetch w2 chunk 0

    // A = ff^T fragments (rows n)
    float zjv[4];
#pragma unroll
    for (int k = 0; k < 4; k++) zjv[k] = __ldg(z + 32 * w + gid + 8 * k);
    {
        uint32_t af[2][8][4];
#pragma unroll
        for (int km = 0; km < 4; km++)
#pragma unroll
            for (int ac = 0; ac < 2; ac++) {
                int kb = 8 * km + tig + 4 * ac;
                float cf = __ldg(icoef + kb);
#pragma unroll
                for (int mm = 0; mm < 2; mm++)
#pragma unroll
                    for (int ar = 0; ar < 2; ar++) {
                        float s, c;
                        __sincosf(TWO_PI * zjv[mm * 2 + ar] * cf, &s, &c);
                        af[mm][km][ar + 2 * ac]     = cvt_tf32(c);
                        af[mm][km + 4][ar + 2 * ac] = cvt_tf32(s);
                    }
            }
        __syncthreads();   // TB (w1^T) staged

        // stage 1: C[n][d] quarters -> tanh -> his[d][n]
#pragma unroll
        for (int q = 0; q < 4; q++) {
            float C[2][2][4];
#pragma unroll
            for (int mm = 0; mm < 2; mm++)
#pragma unroll
                for (int nb = 0; nb < 2; nb++)
#pragma unroll
                    for (int jj = 0; jj < 4; jj++) C[mm][nb][jj] = 0.f;
#pragma unroll
            for (int ks = 0; ks < 8; ks++) {
                uint2 b0 = *(const uint2*)(TB + (ks * 8 + 2 * q)     * 66 + lane * 2);
                uint2 b1 = *(const uint2*)(TB + (ks * 8 + 2 * q + 1) * 66 + lane * 2);
                mma8(C[0][0], af[0][ks], b0.x, b0.y);
                mma8(C[0][1], af[0][ks], b1.x, b1.y);
                mma8(C[1][0], af[1][ks], b0.x, b0.y);
                mma8(C[1][1], af[1][ks], b1.x, b1.y);
            }
#pragma unroll
            for (int mm = 0; mm < 2; mm++)
#pragma unroll
                for (int nb = 0; nb < 2; nb++)
#pragma unroll
                    for (int jj = 0; jj < 4; jj++) {
                        int d = 16 * q + 8 * nb + 2 * tig + (jj & 1);
                        int n = 32 * w + 16 * mm + 8 * (jj >> 1) + gid;
                        his[d * 264 + n] = cvt_tf32(fast_tanh(C[mm][nb][jj]));
                    }
        }
    }
    __syncthreads();   // his complete; TB reads done

    // hi A-fragments from his (conflict-free: bank = 8*tig + gid + ...)
    uint32_t af2[2][8][4];
#pragma unroll
    for (int mm = 0; mm < 2; mm++)
#pragma unroll
        for (int ks = 0; ks < 8; ks++)
#pragma unroll
            for (int ac = 0; ac < 2; ac++)
#pragma unroll
                for (int ar = 0; ar < 2; ar++)
                    af2[mm][ks][ar + 2 * ac] =
                        his[(ks * 8 + tig + 4 * ac) * 264 + 32 * w + 16 * mm + 8 * ar + gid];

    store_tileBT(TB, tr, t);            // w2 chunk 0
    load_tile4(tr, w2g + 4096, t);      // prefetch chunk 1
    __syncthreads();                    // af2 loads done (in-reg), TB ready

    float mrow[4], srow[4];
#pragma unroll
    for (int r = 0; r < 4; r++) { mrow[r] = NEG_INF; srow[r] = 0.f; }

    float* og = out + (size_t)g * (NIPV * 256);
    float4* og4 = (float4*)og;

#pragma unroll 1
    for (int cb = 0; cb < 4; cb++) {
#pragma unroll
        for (int q = 0; q < 4; q++) {
            float C[2][2][4];
#pragma unroll
            for (int mm = 0; mm < 2; mm++)
#pragma unroll
                for (int nb = 0; nb < 2; nb++)
#pragma unroll
                    for (int jj = 0; jj < 4; jj++) C[mm][nb][jj] = 0.f;
#pragma unroll
            for (int ks = 0; ks < 8; ks++) {
                uint2 b0 = *(const uint2*)(TB + (ks * 8 + 2 * q)     * 66 + lane * 2);
                uint2 b1 = *(const uint2*)(TB + (ks * 8 + 2 * q + 1) * 66 + lane * 2);
                mma8(C[0][0], af2[0][ks], b0.x, b0.y);
                mma8(C[0][1], af2[0][ks], b1.x, b1.y);
                mma8(C[1][0], af2[1][ks], b0.x, b0.y);
                mma8(C[1][1], af2[1][ks], b1.x, b1.y);
            }
            // online lse per row + stash to tbuf
#pragma unroll
            for (int mm = 0; mm < 2; mm++)
#pragma unroll
                for (int nb = 0; nb < 2; nb++)
#pragma unroll
                    for (int jj = 0; jj < 4; jj++) {
                        float v = C[mm][nb][jj];
                        int rr = jj >> 1, ridx = 2 * mm + rr;
                        float nm = fmaxf(mrow[ridx], v);
                        srow[ridx] = srow[ridx] * __expf(mrow[ridx] - nm) + __expf(v - nm);
                        mrow[ridx] = nm;
                        int n = 32 * w + 16 * mm + 8 * rr + gid;
                        tbuf[n * 20 + 8 * nb + 2 * tig + (jj & 1)] = v;
                    }
            if (q == 3 && cb < 3) { }   // (TB restaged after sync below)
            __syncthreads();
            // coalesced copy: out[g, n, cb*64 + q*16 + c]
#pragma unroll
            for (int r = 0; r < 4; r++) {
                int f4 = t + 256 * r;
                int n = f4 >> 2, c4 = f4 & 3;
                float4 v = *(float4*)(tbuf + n * 20 + c4 * 4);
                og4[(size_t)n * 64 + cb * 16 + q * 4 + c4] = v;
            }
            if (q == 3 && cb < 3) {
                store_tileBT(TB, tr, t);                            // chunk cb+1
                if (cb < 2) load_tile4(tr, w2g + (size_t)(cb + 2) * 4096, t);
            }
            __syncthreads();
        }
    }

    // merge (max,sum) over tig lanes -> full c range
#pragma unroll
    for (int r = 0; r < 4; r++) {
#pragma unroll
        for (int o = 1; o <= 2; o <<= 1) {
            float mo = __shfl_xor_sync(0xffffffffu, mrow[r], o);
            float so = __shfl_xor_sync(0xffffffffu, srow[r], o);
            float nm = fmaxf(mrow[r], mo);
            srow[r] = srow[r] * __expf(mrow[r] - nm) + so * __expf(mo - nm);
            mrow[r] = nm;
        }
    }
    if (tig == 0) {
#pragma unroll
        for (int mm = 0; mm < 2; mm++)
#pragma unroll
            for (int rr = 0; rr < 2; rr++) {
                int ridx = 2 * mm + rr;
                lseb[32 * w + 16 * mm + 8 * rr + gid] = mrow[ridx] + __logf(srow[ridx]);
            }
    }
    __syncthreads();

    // fused log-softmax subtract (L2-hot reread)
#pragma unroll 4
    for (int r = 0; r < 64; r++) {
        int idx = t + 256 * r;
        float l = lseb[idx >> 6];
        float4 v = og4[idx];
        v.x -= l; v.y -= l; v.z -= l; v.w -= l;
        og4[idx] = v;
    }
}

// ===========================================================================
__global__ __launch_bounds__(256, 2) void mega2_kernel(
    const float* __restrict__ z, const float* __restrict__ log_w,
    const float* __restrict__ icoef, const float* __restrict__ iw1,
    const float* __restrict__ iw2,
    const float* __restrict__ incoef, const float* __restrict__ inw1,
    const float* __restrict__ inw2,
    float* __restrict__ out_inner, float* __restrict__ out_input)
{
    extern __shared__ float sm[];
    if (blockIdx.x < 512)
        inner_path(sm, blockIdx.x, z, log_w, icoef, iw1, iw2, out_inner);
    else
        input_path(sm, blockIdx.x - 512, z, incoef, inw1, inw2, out_input);
}

extern "C" void kernel_launch(void* const* d_in, const int* in_sizes, int n_in,
                              void* d_out, int out_size) {
    const float* z      = (const float*)d_in[0];
    const float* log_w  = (const float*)d_in[1];
    const float* icoef  = (const float*)d_in[2];
    const float* iw1    = (const float*)d_in[3];
    const float* iw2    = (const float*)d_in[4];
    const float* incoef = (const float*)d_in[5];
    const float* inw1   = (const float*)d_in[6];
    const float* inw2   = (const float*)d_in[7];

    float* out = (float*)d_out;
    float* out_input = out + (size_t)NINNER * NIPV * NIPV;

    const int SMEM = 21376 * (int)sizeof(float);   // 85,504 B (input path max)
    cudaFuncSetAttribute(mega2_kernel, cudaFuncAttributeMaxDynamicSharedMemorySize, SMEM);

    mega2_kernel<<<512 + NINPUT, 256, SMEM>>>(z, log_w, icoef, iw1, iw2,
                                              incoef, inw1, inw2, out, out_input);
}

// round 11
// speedup vs baseline: 1.3417x; 1.1585x over previous
#include <cuda_runtime.h>
#include <cuda_fp16.h>
#include <cstdint>
#include <math.h>

#define NIPV    256
#define NINNER  16
#define NINPUT  784
#define NDIM    64
#define TWO_PI  6.28318530717958647692f
#define NEG_INF __int_as_float(0xff800000)

// ---------------------------------------------------------------------------
__device__ __forceinline__ uint32_t pack_h2(float a, float b) {
    __half2 h = __floats2half2_rn(a, b);
    return *reinterpret_cast<uint32_t*>(&h);
}
__device__ __forceinline__ void mma16(float* c, const uint32_t* a, uint32_t b0, uint32_t b1) {
    asm volatile("mma.sync.aligned.m16n8k16.row.col.f32.f16.f16.f32 "
        "{%0,%1,%2,%3}, {%4,%5,%6,%7}, {%8,%9}, {%0,%1,%2,%3};"
        : "+f"(c[0]), "+f"(c[1]), "+f"(c[2]), "+f"(c[3])
        : "r"(a[0]), "r"(a[1]), "r"(a[2]), "r"(a[3]), "r"(b0), "r"(b1));
}
__device__ __forceinline__ float fast_tanh(float x) {
    float e = __expf(2.0f * x);
    return 1.0f - __fdividef(2.0f, e + 1.0f);
}
__device__ __forceinline__ float softplus_f(float x) {
    return fmaxf(x, 0.f) + log1pf(__expf(-fabsf(x)));
}
__device__ __forceinline__ void load_tile4(float4 v[4], const float* src, int t) {
    const float4* s4 = (const float4*)src;
#pragma unroll
    for (int r = 0; r < 4; r++) v[r] = s4[t + 256 * r];
}
// Stage 64x64 fp32 tile -> fp16 B-frag layout (2112 u32 words).
// word ADDR(d, kp) = (((kp>>3)*4 + (kp&3))*66 + d)*2 + ((kp>>2)&1),  kp = k>>1
// Load for (ks, nbg): uint2 at (((ks*4+tig)*66 + nbg*8 + gid) << 1) = {b0, b1}.
__device__ __forceinline__ void store_tileBTh(uint32_t* dst, const float4 v[4], int t) {
#pragma unroll
    for (int r = 0; r < 4; r++) {
        int f4 = t + 256 * r;
        int d = f4 >> 4, c4 = f4 & 15;
        int kp0 = 2 * c4, kp1 = 2 * c4 + 1;
        dst[((((kp0 >> 3) * 4 + (kp0 & 3)) * 66 + d) << 1) + ((kp0 >> 2) & 1)] = pack_h2(v[r].x, v[r].y);
        dst[((((kp1 >> 3) * 4 + (kp1 & 3)) * 66 + d) << 1) + ((kp1 >> 2) & 1)] = pack_h2(v[r].z, v[r].w);
    }
}

// ===========================================================================
// Inner path: ff (fp16) regs as A, w1^T fp16 as B per g, d quarters.
// smem(words): TB0 2112 | TB1 2112 | w2s 512 | lws 256 | vbuf 2080 | lseb 8
//   = 7080 words
// ===========================================================================
__device__ void inner_path(float* sm, int bx,
    const float* __restrict__ z, const float* __restrict__ log_w,
    const float* __restrict__ icoef, const float* __restrict__ w1,
    const float* __restrict__ w2, float* __restrict__ out)
{
    uint32_t* TB0 = (uint32_t*)sm;
    uint32_t* TB1 = TB0 + 2112;
    float* w2s  = sm + 4224;
    float* lws  = sm + 4736;
    float* vbuf = sm + 4992;    // [8][260]
    float* lseb = sm + 7072;

    const int t = threadIdx.x, lane = t & 31, w = t >> 5;
    const int gid = lane >> 2, tig = lane & 3;
    const int i = bx >> 1, gh = bx & 1;

    float4 tr[4];
    load_tile4(tr, w1 + (size_t)(gh * 8) * 4096, t);

    const float zi = z[i];
    float zjv[4];
#pragma unroll
    for (int k = 0; k < 4; k++) zjv[k] = __ldg(z + 32 * w + gid + 8 * k);

    // A-frags: af[mm][ks(4)][ar + 2*kh], half2 = features (k0, k0+1) of row j
    uint32_t af[2][4][4];
#pragma unroll
    for (int ksl = 0; ksl < 2; ksl++)
#pragma unroll
        for (int kh = 0; kh < 2; kh++) {
            int k0 = 16 * ksl + 8 * kh + 2 * tig;
            float c0 = __ldg(icoef + k0),      c1 = __ldg(icoef + k0 + 1);
            float d0 = __ldg(icoef + 32 + k0), d1 = __ldg(icoef + 32 + k0 + 1);
#pragma unroll
            for (int mm = 0; mm < 2; mm++)
#pragma unroll
                for (int ar = 0; ar < 2; ar++) {
                    float s0, co0, s1, co1;
                    __sincosf(TWO_PI * fmaf(zi, c0, zjv[2 * mm + ar] * d0), &s0, &co0);
                    __sincosf(TWO_PI * fmaf(zi, c1, zjv[2 * mm + ar] * d1), &s1, &co1);
                    af[mm][ksl][ar + 2 * kh]     = pack_h2(co0, co1);
                    af[mm][ksl + 2][ar + 2 * kh] = pack_h2(s0, s1);
                }
        }

    for (int idx = t; idx < 512; idx += 256) w2s[idx] = w2[gh * 512 + idx];
    lws[t] = log_w[t];
    store_tileBTh(TB0, tr, t);
    __syncthreads();

#pragma unroll 1
    for (int gl = 0; gl < 8; gl++) {
        const uint32_t* TB = (gl & 1) ? TB1 : TB0;
        if (gl < 7) load_tile4(tr, w1 + (size_t)(gh * 8 + gl + 1) * 4096, t);

        float pc[2][2] = {{0.f, 0.f}, {0.f, 0.f}};
#pragma unroll
        for (int q = 0; q < 4; q++) {
            float C[2][2][4];
#pragma unroll
            for (int mm = 0; mm < 2; mm++)
#pragma unroll
                for (int nb = 0; nb < 2; nb++)
#pragma unroll
                    for (int jj = 0; jj < 4; jj++) C[mm][nb][jj] = 0.f;
#pragma unroll
            for (int ks = 0; ks < 4; ks++)
#pragma unroll
                for (int nb = 0; nb < 2; nb++) {
                    uint2 b = *(const uint2*)(TB + (((ks * 4 + tig) * 66 + (2 * q + nb) * 8 + gid) << 1));
                    mma16(C[0][nb], af[0][ks], b.x, b.y);
                    mma16(C[1][nb], af[1][ks], b.x, b.y);
                }
#pragma unroll
            for (int mm = 0; mm < 2; mm++)
#pragma unroll
                for (int nb = 0; nb < 2; nb++)
#pragma unroll
                    for (int jj = 0; jj < 4; jj++) {
                        int d = 16 * q + 8 * nb + 2 * tig + (jj & 1);
                        pc[mm][jj >> 1] += w2s[gl * 64 + d] * fast_tanh(C[mm][nb][jj]);
                    }
        }
#pragma unroll
        for (int mm = 0; mm < 2; mm++)
#pragma unroll
            for (int ar = 0; ar < 2; ar++) {
                pc[mm][ar] += __shfl_xor_sync(0xffffffffu, pc[mm][ar], 1);
                pc[mm][ar] += __shfl_xor_sync(0xffffffffu, pc[mm][ar], 2);
            }
        if (tig == 0) {
#pragma unroll
            for (int mm = 0; mm < 2; mm++)
#pragma unroll
                for (int ar = 0; ar < 2; ar++) {
                    int j = 32 * w + 16 * mm + 8 * ar + gid;
                    vbuf[gl * 260 + j] = lws[j] - softplus_f(pc[mm][ar]);
                }
        }
        if (gl < 7) store_tileBTh((gl & 1) ? TB0 : TB1, tr, t);
        __syncthreads();
    }

    {
        const float* row = vbuf + w * 260;
        float mx = NEG_INF;
#pragma unroll
        for (int k = 0; k < 8; k++) mx = fmaxf(mx, row[lane + 32 * k]);
#pragma unroll
        for (int o = 16; o > 0; o >>= 1) mx = fmaxf(mx, __shfl_xor_sync(0xffffffffu, mx, o));
        float ssum = 0.f;
#pragma unroll
        for (int k = 0; k < 8; k++) ssum += __expf(row[lane + 32 * k] - mx);
#pragma unroll
        for (int o = 16; o > 0; o >>= 1) ssum += __shfl_xor_sync(0xffffffffu, ssum, o);
        if (lane == 0) lseb[w] = mx + __logf(ssum);
    }
    __syncthreads();

#pragma unroll
    for (int lg = 0; lg < 8; lg++)
        out[(size_t)(gh * 8 + lg) * (NIPV * NIPV) + (size_t)t * NIPV + i] =
            __expf(vbuf[lg * 260 + t] - lseb[lg]);
}

// ===========================================================================
// Input path: fp16 A in regs, fp16 weights via BT-h layout.
// smem(words): TB 2112 | his 8448 ([32 dp][264] half2; tbuf [256][20] aliases)
//   | lseb 256  = 10816 words = 43,264 B
// ===========================================================================
__device__ void input_path(float* sm, int g,
    const float* __restrict__ z, const float* __restrict__ icoef,
    const float* __restrict__ w1, const float* __restrict__ w2,
    float* __restrict__ out)
{
    uint32_t* TB  = (uint32_t*)sm;           // 2112
    uint32_t* his = (uint32_t*)sm + 2112;    // 8448
    float* tbuf = sm + 2112;                 // aliases his: [256][20]
    float* lseb = sm + 10560;

    const int t = threadIdx.x, lane = t & 31, w = t >> 5;
    const int gid = lane >> 2, tig = lane & 3;
    const float* w2g = w2 + (size_t)g * 16384;

    float4 tr[4];
    load_tile4(tr, w1 + (size_t)g * 4096, t);
    store_tileBTh(TB, tr, t);
    load_tile4(tr, w2g, t);   // prefetch w2 chunk 0

    float zjv[4];
#pragma unroll
    for (int k = 0; k < 4; k++) zjv[k] = __ldg(z + 32 * w + gid + 8 * k);
    {
        uint32_t af[2][4][4];
#pragma unroll
        for (int ksl = 0; ksl < 2; ksl++)
#pragma unroll
            for (int kh = 0; kh < 2; kh++) {
                int k0 = 16 * ksl + 8 * kh + 2 * tig;
                float c0 = __ldg(icoef + k0), c1 = __ldg(icoef + k0 + 1);
#pragma unroll
                for (int mm = 0; mm < 2; mm++)
#pragma unroll
                    for (int ar = 0; ar < 2; ar++) {
                        float s0, co0, s1, co1;
                        __sincosf(TWO_PI * zjv[2 * mm + ar] * c0, &s0, &co0);
                        __sincosf(TWO_PI * zjv[2 * mm + ar] * c1, &s1, &co1);
                        af[mm][ksl][ar + 2 * kh]     = pack_h2(co0, co1);
                        af[mm][ksl + 2][ar + 2 * kh] = pack_h2(s0, s1);
                    }
            }
        __syncthreads();   // TB (w1^T) staged

        // stage 1: C[n][d] quarters -> tanh -> his[dp][n] (half2 over d)
#pragma unroll
        for (int q = 0; q < 4; q++) {
            float C[2][2][4];
#pragma unroll
            for (int mm = 0; mm < 2; mm++)
#pragma unroll
                for (int nb = 0; nb < 2; nb++)
#pragma unroll
                    for (int jj = 0; jj < 4; jj++) C[mm][nb][jj] = 0.f;
#pragma unroll
            for (int ks = 0; ks < 4; ks++)
#pragma unroll
                for (int nb = 0; nb < 2; nb++) {
                    uint2 b = *(const uint2*)(TB + (((ks * 4 + tig) * 66 + (2 * q + nb) * 8 + gid) << 1));
                    mma16(C[0][nb], af[0][ks], b.x, b.y);
                    mma16(C[1][nb], af[1][ks], b.x, b.y);
                }
#pragma unroll
            for (int mm = 0; mm < 2; mm++)
#pragma unroll
                for (int nb = 0; nb < 2; nb++)
#pragma unroll
                    for (int rr = 0; rr < 2; rr++) {
                        int dp = 8 * q + 4 * nb + tig;
                        int n = 32 * w + 16 * mm + 8 * rr + gid;
                        his[dp * 264 + n] = pack_h2(fast_tanh(C[mm][nb][2 * rr]),
                                                    fast_tanh(C[mm][nb][2 * rr + 1]));
                    }
        }
    }
    __syncthreads();   // his complete; TB reads done

    // hi A-fragments from his (conflict-free: bank = 8*tig + gid)
    uint32_t af2[2][4][4];
#pragma unroll
    for (int mm = 0; mm < 2; mm++)
#pragma unroll
        for (int ks = 0; ks < 4; ks++)
#pragma unroll
            for (int kh = 0; kh < 2; kh++)
#pragma unroll
                for (int ar = 0; ar < 2; ar++)
                    af2[mm][ks][ar + 2 * kh] =
                        his[(8 * ks + 4 * kh + tig) * 264 + 32 * w + 16 * mm + 8 * ar + gid];

    store_tileBTh(TB, tr, t);            // w2 chunk 0
    load_tile4(tr, w2g + 4096, t);       // prefetch chunk 1
    __syncthreads();

    float mrow[4], srow[4];
#pragma unroll
    for (int r = 0; r < 4; r++) { mrow[r] = NEG_INF; srow[r] = 0.f; }

    float* og = out + (size_t)g * (NIPV * 256);
    float4* og4 = (float4*)og;

#pragma unroll 1
    for (int cb = 0; cb < 4; cb++) {
#pragma unroll
        for (int q = 0; q < 4; q++) {
            float C[2][2][4];
#pragma unroll
            for (int mm = 0; mm < 2; mm++)
#pragma unroll
                for (int nb = 0; nb < 2; nb++)
#pragma unroll
                    for (int jj = 0; jj < 4; jj++) C[mm][nb][jj] = 0.f;
#pragma unroll
            for (int ks = 0; ks < 4; ks++)
#pragma unroll
                for (int nb = 0; nb < 2; nb++) {
                    uint2 b = *(const uint2*)(TB + (((ks * 4 + tig) * 66 + (2 * q + nb) * 8 + gid) << 1));
                    mma16(C[0][nb], af2[0][ks], b.x, b.y);
                    mma16(C[1][nb], af2[1][ks], b.x, b.y);
                }
            // online lse per row + stash to tbuf
#pragma unroll
            for (int mm = 0; mm < 2; mm++)
#pragma unroll
                for (int nb = 0; nb < 2; nb++)
#pragma unroll
                    for (int jj = 0; jj < 4; jj++) {
                        float v = C[mm][nb][jj];
                        int rr = jj >> 1, ridx = 2 * mm + rr;
                        float nm = fmaxf(mrow[ridx], v);
                        srow[ridx] = srow[ridx] * __expf(mrow[ridx] - nm) + __expf(v - nm);
                        mrow[ridx] = nm;
                        int n = 32 * w + 16 * mm + 8 * rr + gid;
                        tbuf[n * 20 + 8 * nb + 2 * tig + (jj & 1)] = v;
                    }
            __syncthreads();
#pragma unroll
            for (int r = 0; r < 4; r++) {
                int f4 = t + 256 * r;
                int n = f4 >> 2, c4 = f4 & 3;
                float4 v = *(float4*)(tbuf + n * 20 + c4 * 4);
                og4[(size_t)n * 64 + cb * 16 + q * 4 + c4] = v;
            }
            if (q == 3 && cb < 3) {
                store_tileBTh(TB, tr, t);                           // chunk cb+1
                if (cb < 2) load_tile4(tr, w2g + (size_t)(cb + 2) * 4096, t);
            }
            __syncthreads();
        }
    }

    // merge (max,sum) over tig lanes -> full c range
#pragma unroll
    for (int r = 0; r < 4; r++) {
#pragma unroll
        for (int o = 1; o <= 2; o <<= 1) {
            float mo = __shfl_xor_sync(0xffffffffu, mrow[r], o);
            float so = __shfl_xor_sync(0xffffffffu, srow[r], o);
            float nm = fmaxf(mrow[r], mo);
            srow[r] = srow[r] * __expf(mrow[r] - nm) + so * __expf(mo - nm);
            mrow[r] = nm;
        }
    }
    if (tig == 0) {
#pragma unroll
        for (int mm = 0; mm < 2; mm++)
#pragma unroll
            for (int rr = 0; rr < 2; rr++) {
                int ridx = 2 * mm + rr;
                lseb[32 * w + 16 * mm + 8 * rr + gid] = mrow[ridx] + __logf(srow[ridx]);
            }
    }
    __syncthreads();

    // fused log-softmax subtract (L2-hot reread)
#pragma unroll 4
    for (int r = 0; r < 64; r++) {
        int idx = t + 256 * r;
        float l = lseb[idx >> 6];
        float4 v = og4[idx];
        v.x -= l; v.y -= l; v.z -= l; v.w -= l;
        og4[idx] = v;
    }
}

// ===========================================================================
__global__ __launch_bounds__(256, 3) void mega2_kernel(
    const float* __restrict__ z, const float* __restrict__ log_w,
    const float* __restrict__ icoef, const float* __restrict__ iw1,
    const float* __restrict__ iw2,
    const float* __restrict__ incoef, const float* __restrict__ inw1,
    const float* __restrict__ inw2,
    float* __restrict__ out_inner, float* __restrict__ out_input)
{
    extern __shared__ float sm[];
    if (blockIdx.x < 512)
        inner_path(sm, blockIdx.x, z, log_w, icoef, iw1, iw2, out_inner);
    else
        input_path(sm, blockIdx.x - 512, z, incoef, inw1, inw2, out_input);
}

extern "C" void kernel_launch(void* const* d_in, const int* in_sizes, int n_in,
                              void* d_out, int out_size) {
    const float* z      = (const float*)d_in[0];
    const float* log_w  = (const float*)d_in[1];
    const float* icoef  = (const float*)d_in[2];
    const float* iw1    = (const float*)d_in[3];
    const float* iw2    = (const float*)d_in[4];
    const float* incoef = (const float*)d_in[5];
    const float* inw1   = (const float*)d_in[6];
    const float* inw2   = (const float*)d_in[7];

    float* out = (float*)d_out;
    float* out_input = out + (size_t)NINNER * NIPV * NIPV;

    const int SMEM = 10816 * (int)sizeof(float);   // 43,264 B
    cudaFuncSetAttribute(mega2_kernel, cudaFuncAttributeMaxDynamicSharedMemorySize, SMEM);

    mega2_kernel<<<512 + NINPUT, 256, SMEM>>>(z, log_w, icoef, iw1, iw2,
                                              incoef, inw1, inw2, out, out_input);
}

// round 12
// speedup vs baseline: 1.7365x; 1.2942x over previous
#include <cuda_runtime.h>
#include <cuda_fp16.h>
#include <cstdint>
#include <math.h>

#define NIPV    256
#define NINNER  16
#define NINPUT  784
#define NDIM    64
#define TWO_PI  6.28318530717958647692f
#define NEG_INF __int_as_float(0xff800000)

// ---------------------------------------------------------------------------
__device__ __forceinline__ uint32_t pack_h2(float a, float b) {
    __half2 h = __floats2half2_rn(a, b);
    return *reinterpret_cast<uint32_t*>(&h);
}
__device__ __forceinline__ void mma16(float* c, const uint32_t* a, uint32_t b0, uint32_t b1) {
    asm volatile("mma.sync.aligned.m16n8k16.row.col.f32.f16.f16.f32 "
        "{%0,%1,%2,%3}, {%4,%5,%6,%7}, {%8,%9}, {%0,%1,%2,%3};"
        : "+f"(c[0]), "+f"(c[1]), "+f"(c[2]), "+f"(c[3])
        : "r"(a[0]), "r"(a[1]), "r"(a[2]), "r"(a[3]), "r"(b0), "r"(b1));
}
__device__ __forceinline__ float fast_tanh(float x) {
    float e = __expf(2.0f * x);
    return 1.0f - __fdividef(2.0f, e + 1.0f);
}
__device__ __forceinline__ float softplus_f(float x) {
    return fmaxf(x, 0.f) + log1pf(__expf(-fabsf(x)));
}
__device__ __forceinline__ void load_tile4(float4 v[4], const float* src, int t) {
    const float4* s4 = (const float4*)src;
#pragma unroll
    for (int r = 0; r < 4; r++) v[r] = s4[t + 256 * r];
}
// Stage 64x64 fp32 tile -> fp16 B-frag layout (2112 u32 words).
__device__ __forceinline__ void store_tileBTh(uint32_t* dst, const float4 v[4], int t) {
#pragma unroll
    for (int r = 0; r < 4; r++) {
        int f4 = t + 256 * r;
        int d = f4 >> 4, c4 = f4 & 15;
        int kp0 = 2 * c4, kp1 = 2 * c4 + 1;
        dst[((((kp0 >> 3) * 4 + (kp0 & 3)) * 66 + d) << 1) + ((kp0 >> 2) & 1)] = pack_h2(v[r].x, v[r].y);
        dst[((((kp1 >> 3) * 4 + (kp1 & 3)) * 66 + d) << 1) + ((kp1 >> 2) & 1)] = pack_h2(v[r].z, v[r].w);
    }
}

// ===========================================================================
// Inner path (R11-verified). smem words: TB0 2112 | TB1 2112 | w2s 512
//   | lws 256 | vbuf 2080 | lseb 8  = 7080
// ===========================================================================
__device__ void inner_path(float* sm, int bx,
    const float* __restrict__ z, const float* __restrict__ log_w,
    const float* __restrict__ icoef, const float* __restrict__ w1,
    const float* __restrict__ w2, float* __restrict__ out)
{
    uint32_t* TB0 = (uint32_t*)sm;
    uint32_t* TB1 = TB0 + 2112;
    float* w2s  = sm + 4224;
    float* lws  = sm + 4736;
    float* vbuf = sm + 4992;    // [8][260]
    float* lseb = sm + 7072;

    const int t = threadIdx.x, lane = t & 31, w = t >> 5;
    const int gid = lane >> 2, tig = lane & 3;
    const int i = bx >> 1, gh = bx & 1;

    float4 tr[4];
    load_tile4(tr, w1 + (size_t)(gh * 8) * 4096, t);

    const float zi = z[i];
    float zjv[4];
#pragma unroll
    for (int k = 0; k < 4; k++) zjv[k] = __ldg(z + 32 * w + gid + 8 * k);

    uint32_t af[2][4][4];
#pragma unroll
    for (int ksl = 0; ksl < 2; ksl++)
#pragma unroll
        for (int kh = 0; kh < 2; kh++) {
            int k0 = 16 * ksl + 8 * kh + 2 * tig;
            float c0 = __ldg(icoef + k0),      c1 = __ldg(icoef + k0 + 1);
            float d0 = __ldg(icoef + 32 + k0), d1 = __ldg(icoef + 32 + k0 + 1);
#pragma unroll
            for (int mm = 0; mm < 2; mm++)
#pragma unroll
                for (int ar = 0; ar < 2; ar++) {
                    float s0, co0, s1, co1;
                    __sincosf(TWO_PI * fmaf(zi, c0, zjv[2 * mm + ar] * d0), &s0, &co0);
                    __sincosf(TWO_PI * fmaf(zi, c1, zjv[2 * mm + ar] * d1), &s1, &co1);
                    af[mm][ksl][ar + 2 * kh]     = pack_h2(co0, co1);
                    af[mm][ksl + 2][ar + 2 * kh] = pack_h2(s0, s1);
                }
        }

    for (int idx = t; idx < 512; idx += 256) w2s[idx] = w2[gh * 512 + idx];
    lws[t] = log_w[t];
    store_tileBTh(TB0, tr, t);
    __syncthreads();

#pragma unroll 1
    for (int gl = 0; gl < 8; gl++) {
        const uint32_t* TB = (gl & 1) ? TB1 : TB0;
        if (gl < 7) load_tile4(tr, w1 + (size_t)(gh * 8 + gl + 1) * 4096, t);

        float pc[2][2] = {{0.f, 0.f}, {0.f, 0.f}};
#pragma unroll
        for (int q = 0; q < 4; q++) {
            float C[2][2][4];
#pragma unroll
            for (int mm = 0; mm < 2; mm++)
#pragma unroll
                for (int nb = 0; nb < 2; nb++)
#pragma unroll
                    for (int jj = 0; jj < 4; jj++) C[mm][nb][jj] = 0.f;
#pragma unroll
            for (int ks = 0; ks < 4; ks++)
#pragma unroll
                for (int nb = 0; nb < 2; nb++) {
                    uint2 b = *(const uint2*)(TB + (((ks * 4 + tig) * 66 + (2 * q + nb) * 8 + gid) << 1));
                    mma16(C[0][nb], af[0][ks], b.x, b.y);
                    mma16(C[1][nb], af[1][ks], b.x, b.y);
                }
#pragma unroll
            for (int mm = 0; mm < 2; mm++)
#pragma unroll
                for (int nb = 0; nb < 2; nb++)
#pragma unroll
                    for (int jj = 0; jj < 4; jj++) {
                        int d = 16 * q + 8 * nb + 2 * tig + (jj & 1);
                        pc[mm][jj >> 1] += w2s[gl * 64 + d] * fast_tanh(C[mm][nb][jj]);
                    }
        }
#pragma unroll
        for (int mm = 0; mm < 2; mm++)
#pragma unroll
            for (int ar = 0; ar < 2; ar++) {
                pc[mm][ar] += __shfl_xor_sync(0xffffffffu, pc[mm][ar], 1);
                pc[mm][ar] += __shfl_xor_sync(0xffffffffu, pc[mm][ar], 2);
            }
        if (tig == 0) {
#pragma unroll
            for (int mm = 0; mm < 2; mm++)
#pragma unroll
                for (int ar = 0; ar < 2; ar++) {
                    int j = 32 * w + 16 * mm + 8 * ar + gid;
                    vbuf[gl * 260 + j] = lws[j] - softplus_f(pc[mm][ar]);
                }
        }
        if (gl < 7) store_tileBTh((gl & 1) ? TB0 : TB1, tr, t);
        __syncthreads();
    }

    {
        const float* row = vbuf + w * 260;
        float mx = NEG_INF;
#pragma unroll
        for (int k = 0; k < 8; k++) mx = fmaxf(mx, row[lane + 32 * k]);
#pragma unroll
        for (int o = 16; o > 0; o >>= 1) mx = fmaxf(mx, __shfl_xor_sync(0xffffffffu, mx, o));
        float ssum = 0.f;
#pragma unroll
        for (int k = 0; k < 8; k++) ssum += __expf(row[lane + 32 * k] - mx);
#pragma unroll
        for (int o = 16; o > 0; o >>= 1) ssum += __shfl_xor_sync(0xffffffffu, ssum, o);
        if (lane == 0) lseb[w] = mx + __logf(ssum);
    }
    __syncthreads();

#pragma unroll
    for (int lg = 0; lg < 8; lg++)
        out[(size_t)(gh * 8 + lg) * (NIPV * NIPV) + (size_t)t * NIPV + i] =
            __expf(vbuf[lg * 260 + t] - lseb[lg]);
}

// ===========================================================================
// Input path: all 4 w2 chunks resident; pass A = lse-only, pass B = write
// with subtract, direct STG.64 from fragments. 3 barriers total.
// smem words: TBall 4*2112 = 8448 | his 8448  = 16,896 words = 67,584 B
// ===========================================================================
__device__ void input_path(float* sm, int g,
    const float* __restrict__ z, const float* __restrict__ icoef,
    const float* __restrict__ w1, const float* __restrict__ w2,
    float* __restrict__ out)
{
    uint32_t* TBall = (uint32_t*)sm;          // 4 x 2112 (slot0 = w1 first)
    uint32_t* his   = (uint32_t*)sm + 8448;   // [32 dp][264] half2

    const int t = threadIdx.x, lane = t & 31, w = t >> 5;
    const int gid = lane >> 2, tig = lane & 3;
    const float* w2g = w2 + (size_t)g * 16384;

    float4 tr[4];
    load_tile4(tr, w1 + (size_t)g * 4096, t);
    store_tileBTh(TBall, tr, t);              // w1 -> slot 0
    load_tile4(tr, w2g + 4096, t);            // chunk 1 LDG (latency hidden)

    float zjv[4];
#pragma unroll
    for (int k = 0; k < 4; k++) zjv[k] = __ldg(z + 32 * w + gid + 8 * k);

    uint32_t af[2][4][4];
#pragma unroll
    for (int ksl = 0; ksl < 2; ksl++)
#pragma unroll
        for (int kh = 0; kh < 2; kh++) {
            int k0 = 16 * ksl + 8 * kh + 2 * tig;
            float c0 = __ldg(icoef + k0), c1 = __ldg(icoef + k0 + 1);
#pragma unroll
            for (int mm = 0; mm < 2; mm++)
#pragma unroll
                for (int ar = 0; ar < 2; ar++) {
                    float s0, co0, s1, co1;
                    __sincosf(TWO_PI * zjv[2 * mm + ar] * c0, &s0, &co0);
                    __sincosf(TWO_PI * zjv[2 * mm + ar] * c1, &s1, &co1);
                    af[mm][ksl][ar + 2 * kh]     = pack_h2(co0, co1);
                    af[mm][ksl + 2][ar + 2 * kh] = pack_h2(s0, s1);
                }
        }

    store_tileBTh(TBall + 2112, tr, t);       // chunk 1 -> slot 1
    load_tile4(tr, w2g + 8192, t);
    store_tileBTh(TBall + 2 * 2112, tr, t);   // chunk 2 -> slot 2
    load_tile4(tr, w2g + 12288, t);
    store_tileBTh(TBall + 3 * 2112, tr, t);   // chunk 3 -> slot 3
    __syncthreads();                          // slot 0 (w1) visible

    // ---- stage 1: C[n][d] quarters -> tanh -> his[dp][n]
#pragma unroll
    for (int q = 0; q < 4; q++) {
        float C[2][2][4];
#pragma unroll
        for (int mm = 0; mm < 2; mm++)
#pragma unroll
            for (int nb = 0; nb < 2; nb++)
#pragma unroll
                for (int jj = 0; jj < 4; jj++) C[mm][nb][jj] = 0.f;
#pragma unroll
        for (int ks = 0; ks < 4; ks++)
#pragma unroll
            for (int nb = 0; nb < 2; nb++) {
                uint2 b = *(const uint2*)(TBall + (((ks * 4 + tig) * 66 + (2 * q + nb) * 8 + gid) << 1));
                mma16(C[0][nb], af[0][ks], b.x, b.y);
                mma16(C[1][nb], af[1][ks], b.x, b.y);
            }
#pragma unroll
        for (int mm = 0; mm < 2; mm++)
#pragma unroll
            for (int nb = 0; nb < 2; nb++)
#pragma unroll
                for (int rr = 0; rr < 2; rr++) {
                    int dp = 8 * q + 4 * nb + tig;
                    int n = 32 * w + 16 * mm + 8 * rr + gid;
                    his[dp * 264 + n] = pack_h2(fast_tanh(C[mm][nb][2 * rr]),
                                                fast_tanh(C[mm][nb][2 * rr + 1]));
                }
    }
    load_tile4(tr, w2g, t);                   // chunk 0 LDG
    __syncthreads();                          // his complete; slot-0 reads done

    // hi A-fragments from his
    uint32_t af2[2][4][4];
#pragma unroll
    for (int mm = 0; mm < 2; mm++)
#pragma unroll
        for (int ks = 0; ks < 4; ks++)
#pragma unroll
            for (int kh = 0; kh < 2; kh++)
#pragma unroll
                for (int ar = 0; ar < 2; ar++)
                    af2[mm][ks][ar + 2 * kh] =
                        his[(8 * ks + 4 * kh + tig) * 264 + 32 * w + 16 * mm + 8 * ar + gid];

    store_tileBTh(TBall, tr, t);              // chunk 0 -> slot 0
    __syncthreads();                          // all 4 chunks resident

    // ---- pass A: online lse only
    float mrow[4], srow[4];
#pragma unroll
    for (int r = 0; r < 4; r++) { mrow[r] = NEG_INF; srow[r] = 0.f; }

#pragma unroll 1
    for (int cb = 0; cb < 4; cb++) {
        const uint32_t* TB = TBall + cb * 2112;
#pragma unroll
        for (int q = 0; q < 4; q++) {
            float C[2][2][4];
#pragma unroll
            for (int mm = 0; mm < 2; mm++)
#pragma unroll
                for (int nb = 0; nb < 2; nb++)
#pragma unroll
                    for (int jj = 0; jj < 4; jj++) C[mm][nb][jj] = 0.f;
#pragma unroll
            for (int ks = 0; ks < 4; ks++)
#pragma unroll
                for (int nb = 0; nb < 2; nb++) {
                    uint2 b = *(const uint2*)(TB + (((ks * 4 + tig) * 66 + (2 * q + nb) * 8 + gid) << 1));
                    mma16(C[0][nb], af2[0][ks], b.x, b.y);
                    mma16(C[1][nb], af2[1][ks], b.x, b.y);
                }
#pragma unroll
            for (int mm = 0; mm < 2; mm++)
#pragma unroll
                for (int nb = 0; nb < 2; nb++)
#pragma unroll
                    for (int jj = 0; jj < 4; jj++) {
                        float v = C[mm][nb][jj];
                        int ridx = 2 * mm + (jj >> 1);
                        float nm = fmaxf(mrow[ridx], v);
                        srow[ridx] = srow[ridx] * __expf(mrow[ridx] - nm) + __expf(v - nm);
                        mrow[ridx] = nm;
                    }
        }
    }
    // merge over tig lanes (all lanes receive merged value)
    float lse[4];
#pragma unroll
    for (int r = 0; r < 4; r++) {
#pragma unroll
        for (int o = 1; o <= 2; o <<= 1) {
            float mo = __shfl_xor_sync(0xffffffffu, mrow[r], o);
            float so = __shfl_xor_sync(0xffffffffu, srow[r], o);
            float nm = fmaxf(mrow[r], mo);
            srow[r] = srow[r] * __expf(mrow[r] - nm) + so * __expf(mo - nm);
            mrow[r] = nm;
        }
        lse[r] = mrow[r] + __logf(srow[r]);
    }

    // ---- pass B: recompute and write (C - lse) via STG.64
    float* og = out + (size_t)g * (NIPV * 256);
#pragma unroll 1
    for (int cb = 0; cb < 4; cb++) {
        const uint32_t* TB = TBall + cb * 2112;
#pragma unroll
        for (int q = 0; q < 4; q++) {
            float C[2][2][4];
#pragma unroll
            for (int mm = 0; mm < 2; mm++)
#pragma unroll
                for (int nb = 0; nb < 2; nb++)
#pragma unroll
                    for (int jj = 0; jj < 4; jj++) C[mm][nb][jj] = 0.f;
#pragma unroll
            for (int ks = 0; ks < 4; ks++)
#pragma unroll
                for (int nb = 0; nb < 2; nb++) {
                    uint2 b = *(const uint2*)(TB + (((ks * 4 + tig) * 66 + (2 * q + nb) * 8 + gid) << 1));
                    mma16(C[0][nb], af2[0][ks], b.x, b.y);
                    mma16(C[1][nb], af2[1][ks], b.x, b.y);
                }
#pragma unroll
            for (int mm = 0; mm < 2; mm++)
#pragma unroll
                for (int rr = 0; rr < 2; rr++) {
                    int n = 32 * w + 16 * mm + 8 * rr + gid;
                    float l = lse[2 * mm + rr];
#pragma unroll
                    for (int nb = 0; nb < 2; nb++) {
                        float2 v;
                        v.x = C[mm][nb][2 * rr]     - l;
                        v.y = C[mm][nb][2 * rr + 1] - l;
                        *(float2*)(og + (size_t)n * 256 + cb * 64 + q * 16 + 8 * nb + 2 * tig) = v;
                    }
                }
        }
    }
}

// ===========================================================================
__global__ __launch_bounds__(256, 3) void mega2_kernel(
    const float* __restrict__ z, const float* __restrict__ log_w,
    const float* __restrict__ icoef, const float* __restrict__ iw1,
    const float* __restrict__ iw2,
    const float* __restrict__ incoef, const float* __restrict__ inw1,
    const float* __restrict__ inw2,
    float* __restrict__ out_inner, float* __restrict__ out_input)
{
    extern __shared__ float sm[];
    if (blockIdx.x < 512)
        inner_path(sm, blockIdx.x, z, log_w, icoef, iw1, iw2, out_inner);
    else
        input_path(sm, blockIdx.x - 512, z, incoef, inw1, inw2, out_input);
}

extern "C" void kernel_launch(void* const* d_in, const int* in_sizes, int n_in,
                              void* d_out, int out_size) {
    const float* z      = (const float*)d_in[0];
    const float* log_w  = (const float*)d_in[1];
    const float* icoef  = (const float*)d_in[2];
    const float* iw1    = (const float*)d_in[3];
    const float* iw2    = (const float*)d_in[4];
    const float* incoef = (const float*)d_in[5];
    const float* inw1   = (const float*)d_in[6];
    const float* inw2   = (const float*)d_in[7];

    float* out = (float*)d_out;
    float* out_input = out + (size_t)NINNER * NIPV * NIPV;

    const int SMEM = 16896 * (int)sizeof(float);   // 67,584 B
    cudaFuncSetAttribute(mega2_kernel, cudaFuncAttributeMaxDynamicSharedMemorySize, SMEM);

    mega2_kernel<<<512 + NINPUT, 256, SMEM>>>(z, log_w, icoef, iw1, iw2,
                                              incoef, inw1, inw2, out, out_input);
}